// round 9
// baseline (speedup 1.0000x reference)
#include <cuda_runtime.h>

#define NROWS 16384
#define K 128
#define D 64
#define RPB 8
#define NBLOCKS (NROWS / RPB)
#define LOG2E 1.4426950408889634f

__device__ __forceinline__ float frcp(float x) {
    float r; asm("rcp.approx.f32 %0, %1;" : "=f"(r) : "f"(x)); return r;
}
__device__ __forceinline__ float fex2(float x) {
    float r; asm("ex2.approx.f32 %0, %1;" : "=f"(r) : "f"(x)); return r;
}
__device__ __forceinline__ float fsqrt_(float x) {
    float r; asm("sqrt.approx.f32 %0, %1;" : "=f"(r) : "f"(x)); return r;
}

// loss = mean_{n,k} exp(-(rank_k-1)/8) * d_k
// rank_k-1 = (sum_all_j a/(a+a_j)) - 0.5,  a = exp(5d-20) (rescaled; ratios invariant)
// Per group of 4 j's, with elementary symmetric polys e1..e4 of (b1..b4):
//   P(a) = prod(a+b_i) via Horner partials h1..h3;  N(a) = P'(a) via g-chain
//   sum_i a/(a+b_i) = a * N * rcp(P)   -> 1 MUFU per 4 pairs
// e's are thread-invariant per (row,group): computed cooperatively once per row.
// All-scalar f32 (f32x2 is cracked on sm_100a; packed form only added overhead).

__global__ __launch_bounds__(128) void dng_kernel(const float* __restrict__ data,
                                                  const float* __restrict__ weights,
                                                  float* __restrict__ out)
{
    __shared__ float4 x_v[RPB][D / 4];       // 8 staged rows
    __shared__ float4 sa_v[RPB][K / 4];      // a_j values, plain layout
    __shared__ float4 e_v[RPB][K / 4];       // per (row,group): {e1,e2,e3,e4}
    __shared__ float x2_s[RPB];
    __shared__ float warp_sums[4];

    float* x_s = (float*)x_v;
    float* saq = (float*)sa_v;

    const int k = threadIdx.x;
    const int lane = k & 31;
    const int wid = k >> 5;

    // weights row k: -2*w in 64 scalar regs + c = |w|^2
    float w[D];
    float c = 0.0f;
    {
        const float4* wp = (const float4*)(weights + k * D);
#pragma unroll
        for (int i = 0; i < D / 4; i++) {
            float4 v = wp[i];
            c = fmaf(v.x, v.x, c); c = fmaf(v.y, v.y, c);
            c = fmaf(v.z, v.z, c); c = fmaf(v.w, v.w, c);
            w[4 * i]     = -2.0f * v.x;
            w[4 * i + 1] = -2.0f * v.y;
            w[4 * i + 2] = -2.0f * v.z;
            w[4 * i + 3] = -2.0f * v.w;
        }
    }

    // ---- phase 1: stage 8 rows + per-row |x|^2 ----
    {
        float4 v = ((const float4*)(data + blockIdx.x * RPB * D))[k];   // row = k>>4
        ((float4*)x_s)[k] = v;
        float p = fmaf(v.x, v.x, fmaf(v.y, v.y, fmaf(v.z, v.z, v.w * v.w)));
#pragma unroll
        for (int o = 8; o; o >>= 1) p += __shfl_down_sync(0xFFFFFFFFu, p, o, 16);
        if ((k & 15) == 0) x2_s[k >> 4] = p;
    }
    __syncthreads();

    // ---- phase 2: 8 independent dots -> dist[r]; a -> smem ----
    float dist[RPB];
#pragma unroll
    for (int r = 0; r < RPB; r++) {
        float d0 = c, d1 = 0.0f, d2a = 0.0f, d3 = 0.0f;
#pragma unroll
        for (int i = 0; i < D / 4; i++) {      // 16 x LDS.128 broadcast
            float4 q = x_v[r][i];
            d0  = fmaf(q.x, w[4 * i],     d0);
            d1  = fmaf(q.y, w[4 * i + 1], d1);
            d2a = fmaf(q.z, w[4 * i + 2], d2a);
            d3  = fmaf(q.w, w[4 * i + 3], d3);
        }
        float d2 = ((d0 + d1) + (d2a + d3)) + x2_s[r];
        float dd = fsqrt_(fmaxf(d2, 0.0f));
        dist[r] = dd;
        saq[r * K + k] = fex2(fmaf(dd, 5.0f * LOG2E, -20.0f * LOG2E));
    }
    __syncthreads();

    // ---- phase 2.5: symmetric polys; 2 (row,group) tasks per thread ----
#pragma unroll
    for (int t = 0; t < 2; t++) {
        const int task = k + t * 128;          // 256 tasks = 8 rows x 32 groups
        const int r = task >> 5, g = task & 31;
        float4 b = sa_v[r][g];
        float s12 = b.x + b.y, p12 = b.x * b.y;
        float s34 = b.z + b.w, p34 = b.z * b.w;
        float4 e;
        e.x = s12 + s34;
        e.y = fmaf(s12, s34, p12 + p34);
        e.z = fmaf(p12, s34, p34 * s12);
        e.w = p12 * p34;
        e_v[r][g] = e;
    }
    __syncthreads();

    // ---- phase 3: rank loops, two rows interleaved, no syncs ----
    float acc = 0.0f;
#pragma unroll
    for (int rp = 0; rp < RPB / 2; rp++) {
        const int r0 = 2 * rp, r1 = 2 * rp + 1;
        const float a0 = fex2(fmaf(dist[r0], 5.0f * LOG2E, -20.0f * LOG2E));
        const float a1 = fex2(fmaf(dist[r1], 5.0f * LOG2E, -20.0f * LOG2E));
        float q0 = 0.0f, q1 = 0.0f;
#pragma unroll
        for (int g = 0; g < K / 4; g++) {
            float4 E0 = e_v[r0][g];            // LDS.128 broadcast
            float4 E1 = e_v[r1][g];
            {   // row r0: P Horner + N derivative chain
                float h1 = a0 + E0.x;
                float h2 = fmaf(h1, a0, E0.y);
                float h3 = fmaf(h2, a0, E0.z);
                float P  = fmaf(h3, a0, E0.w);
                float g2 = h1 + a0;
                float g3 = fmaf(g2, a0, h2);
                float N  = fmaf(g3, a0, h3);
                q0 = fmaf(N, frcp(P), q0);
            }
            {   // row r1 (independent chain)
                float h1 = a1 + E1.x;
                float h2 = fmaf(h1, a1, E1.y);
                float h3 = fmaf(h2, a1, E1.z);
                float P  = fmaf(h3, a1, E1.w);
                float g2 = h1 + a1;
                float g3 = fmaf(g2, a1, h2);
                float N  = fmaf(g3, a1, h3);
                q1 = fmaf(N, frcp(P), q1);
            }
        }
        float rk0 = fmaf(a0, q0, -0.5f);
        float rk1 = fmaf(a1, q1, -0.5f);
        acc = fmaf(fex2(-rk0 * (0.125f * LOG2E)), dist[r0], acc);
        acc = fmaf(fex2(-rk1 * (0.125f * LOG2E)), dist[r1], acc);
    }

    // ---- block reduction -> global atomic ----
#pragma unroll
    for (int o = 16; o; o >>= 1) acc += __shfl_down_sync(0xFFFFFFFFu, acc, o);
    if (lane == 0) warp_sums[wid] = acc;
    __syncthreads();
    if (k == 0) {
        float t = warp_sums[0] + warp_sums[1] + warp_sums[2] + warp_sums[3];
        atomicAdd(out, t * (1.0f / ((float)NROWS * (float)K)));
    }
}

extern "C" void kernel_launch(void* const* d_in, const int* in_sizes, int n_in,
                              void* d_out, int out_size)
{
    const float* data    = (const float*)d_in[0];
    const float* weights = (const float*)d_in[1];
    float* out = (float*)d_out;

    cudaMemsetAsync(out, 0, sizeof(float));
    dng_kernel<<<NBLOCKS, 128>>>(data, weights, out);
}

// round 10
// speedup vs baseline: 1.0021x; 1.0021x over previous
#include <cuda_runtime.h>

#define NROWS 16384
#define K 128
#define D 64
#define RPB 8
#define NBLOCKS_A (NROWS / RPB)
#define RB 4
#define NBLOCKS_B (NROWS / RB)
#define LOG2E 1.4426950408889634f

__device__ __forceinline__ float frcp(float x) {
    float r; asm("rcp.approx.f32 %0, %1;" : "=f"(r) : "f"(x)); return r;
}
__device__ __forceinline__ float fex2(float x) {
    float r; asm("ex2.approx.f32 %0, %1;" : "=f"(r) : "f"(x)); return r;
}
__device__ __forceinline__ float fsqrt_(float x) {
    float r; asm("sqrt.approx.f32 %0, %1;" : "=f"(r) : "f"(x)); return r;
}

// Scratch (static __device__ globals are the sanctioned no-alloc path)
__device__ float  g_dist[NROWS * K];      // 8 MB
__device__ float4 g_E[NROWS * (K / 4)];   // 8 MB: per (row, group-of-4) e1..e4

// loss = mean_{n,k} exp(-(rank_k-1)/8) * d_k
// rank_k-1 = (sum_all_j a/(a+a_j)) - 0.5,  a = exp(5d-20) (rescaled; ratios invariant)
// Group-of-4: P(a)=prod(a+b_i) via Horner on symmetric polys e1..e4; N=P'; sum = a*N*rcp(P).

// ---------- Kernel A: distances + symmetric-poly coefficients ----------
__global__ __launch_bounds__(128) void distA(const float* __restrict__ data,
                                             const float* __restrict__ weights)
{
    __shared__ float4 x_v[RPB][D / 4];
    __shared__ float4 sa_v[RPB][K / 4];
    __shared__ float x2_s[RPB];

    float* x_s = (float*)x_v;
    float* saq = (float*)sa_v;
    const int k = threadIdx.x;
    const int row0 = blockIdx.x * RPB;

    // weights row k: -2*w + |w|^2
    float w[D];
    float c = 0.0f;
    {
        const float4* wp = (const float4*)(weights + k * D);
#pragma unroll
        for (int i = 0; i < D / 4; i++) {
            float4 v = wp[i];
            c = fmaf(v.x, v.x, c); c = fmaf(v.y, v.y, c);
            c = fmaf(v.z, v.z, c); c = fmaf(v.w, v.w, c);
            w[4 * i]     = -2.0f * v.x;
            w[4 * i + 1] = -2.0f * v.y;
            w[4 * i + 2] = -2.0f * v.z;
            w[4 * i + 3] = -2.0f * v.w;
        }
    }

    // stage 8 rows + per-row |x|^2
    {
        float4 v = ((const float4*)(data + row0 * D))[k];   // row = k>>4
        ((float4*)x_s)[k] = v;
        float p = fmaf(v.x, v.x, fmaf(v.y, v.y, fmaf(v.z, v.z, v.w * v.w)));
#pragma unroll
        for (int o = 8; o; o >>= 1) p += __shfl_down_sync(0xFFFFFFFFu, p, o, 16);
        if ((k & 15) == 0) x2_s[k >> 4] = p;
    }
    __syncthreads();

    // 8 dots -> dist (to gmem) + a (to smem)
#pragma unroll
    for (int r = 0; r < RPB; r++) {
        float d0 = c, d1 = 0.0f, d2v = 0.0f, d3 = 0.0f;
#pragma unroll
        for (int i = 0; i < D / 4; i++) {
            float4 q = x_v[r][i];
            d0  = fmaf(q.x, w[4 * i],     d0);
            d1  = fmaf(q.y, w[4 * i + 1], d1);
            d2v = fmaf(q.z, w[4 * i + 2], d2v);
            d3  = fmaf(q.w, w[4 * i + 3], d3);
        }
        float dsq = ((d0 + d1) + (d2v + d3)) + x2_s[r];
        float dd = fsqrt_(fmaxf(dsq, 0.0f));
        g_dist[(row0 + r) * K + k] = dd;
        saq[r * K + k] = fex2(fmaf(dd, 5.0f * LOG2E, -20.0f * LOG2E));
    }
    __syncthreads();

    // symmetric polys: 256 (row,group) tasks, 2 per thread -> gmem
#pragma unroll
    for (int t = 0; t < 2; t++) {
        const int task = k + t * 128;
        const int r = task >> 5, g = task & 31;
        float4 b = sa_v[r][g];
        float s12 = b.x + b.y, p12 = b.x * b.y;
        float s34 = b.z + b.w, p34 = b.z * b.w;
        float4 e;
        e.x = s12 + s34;
        e.y = fmaf(s12, s34, p12 + p34);
        e.z = fmaf(p12, s34, p34 * s12);
        e.w = p12 * p34;
        g_E[(row0 + r) * (K / 4) + g] = e;
    }
}

// ---------- Kernel B: rank phase (high occupancy, 2 centroids/thread) ----------
__global__ __launch_bounds__(256) void rankB(float* __restrict__ out)
{
    __shared__ float4 E_s[RB][K / 4];
    __shared__ float warp_sums[8];

    const int t = threadIdx.x;
    const int rloc = t >> 6;            // 0..3: local row
    const int tk = t & 63;              // centroids tk and tk+64
    const int lane = t & 31;
    const int wid = t >> 5;
    const int row0 = blockIdx.x * RB;

    // stage E (threads 0..127: one float4 each; coalesced)
    if (t < RB * (K / 4))
        ((float4*)E_s)[t] = g_E[row0 * (K / 4) + t];

    const int row = row0 + rloc;
    float d1 = g_dist[row * K + tk];
    float d2 = g_dist[row * K + tk + 64];
    __syncthreads();

    const float a1 = fex2(fmaf(d1, 5.0f * LOG2E, -20.0f * LOG2E));
    const float a2 = fex2(fmaf(d2, 5.0f * LOG2E, -20.0f * LOG2E));
    float q1 = 0.0f, q2 = 0.0f;
#pragma unroll
    for (int g = 0; g < K / 4; g++) {
        float4 E = E_s[rloc][g];        // broadcast LDS.128, serves both chains
        {   // chain for centroid tk
            float h1 = a1 + E.x;
            float h2 = fmaf(h1, a1, E.y);
            float h3 = fmaf(h2, a1, E.z);
            float P  = fmaf(h3, a1, E.w);
            float g2 = h1 + a1;
            float g3 = fmaf(g2, a1, h2);
            float N  = fmaf(g3, a1, h3);
            q1 = fmaf(N, frcp(P), q1);
        }
        {   // chain for centroid tk+64 (independent)
            float h1 = a2 + E.x;
            float h2 = fmaf(h1, a2, E.y);
            float h3 = fmaf(h2, a2, E.z);
            float P  = fmaf(h3, a2, E.w);
            float g2 = h1 + a2;
            float g3 = fmaf(g2, a2, h2);
            float N  = fmaf(g3, a2, h3);
            q2 = fmaf(N, frcp(P), q2);
        }
    }
    float rk1 = fmaf(a1, q1, -0.5f);
    float rk2 = fmaf(a2, q2, -0.5f);
    float acc = fmaf(fex2(-rk1 * (0.125f * LOG2E)), d1,
                     fex2(-rk2 * (0.125f * LOG2E)) * d2);

    // block reduction -> atomic
#pragma unroll
    for (int o = 16; o; o >>= 1) acc += __shfl_down_sync(0xFFFFFFFFu, acc, o);
    if (lane == 0) warp_sums[wid] = acc;
    __syncthreads();
    if (t == 0) {
        float s = 0.0f;
#pragma unroll
        for (int i = 0; i < 8; i++) s += warp_sums[i];
        atomicAdd(out, s * (1.0f / ((float)NROWS * (float)K)));
    }
}

extern "C" void kernel_launch(void* const* d_in, const int* in_sizes, int n_in,
                              void* d_out, int out_size)
{
    const float* data    = (const float*)d_in[0];
    const float* weights = (const float*)d_in[1];
    float* out = (float*)d_out;

    cudaMemsetAsync(out, 0, sizeof(float));
    distA<<<NBLOCKS_A, 128>>>(data, weights);
    rankB<<<NBLOCKS_B, 256>>>(out);
}

// round 11
// speedup vs baseline: 1.2359x; 1.2333x over previous
#include <cuda_runtime.h>

#define NROWS 16384
#define K 128
#define D 64
#define BROWS 32
#define NBLOCKS_A (NROWS / BROWS)
#define RB 4
#define NBLOCKS_B (NROWS / RB)
#define LOG2E 1.4426950408889634f

__device__ __forceinline__ float frcp(float x) {
    float r; asm("rcp.approx.f32 %0, %1;" : "=f"(r) : "f"(x)); return r;
}
__device__ __forceinline__ float fex2(float x) {
    float r; asm("ex2.approx.f32 %0, %1;" : "=f"(r) : "f"(x)); return r;
}
__device__ __forceinline__ float fsqrt_(float x) {
    float r; asm("sqrt.approx.f32 %0, %1;" : "=f"(r) : "f"(x)); return r;
}

// Scratch (__device__ globals: the sanctioned no-alloc path)
__device__ float  g_dist[NROWS * K];      // 8 MB
__device__ float4 g_E[NROWS * (K / 4)];   // 8 MB

// loss = mean_{n,k} exp(-(rank_k-1)/8) * d_k
// rank_k-1 = (sum_all_j a/(a+a_j)) - 0.5,  a = exp(5d-20) (rescaled; ratios invariant)
// Group-of-4: P(a)=prod(a+b_i) Horner on symmetric polys e1..e4; N=P'; sum = a*N*rcp(P).

// ---------- Kernel A: GEMM-tiled distances + a + symmetric polys ----------
__global__ __launch_bounds__(256) void distA(const float* __restrict__ data,
                                             const float* __restrict__ weights)
{
    // layout: X 0..8192 | W 8192..43008 (f4 [col*17+c]) | X2 43008 | W2 43136..43648
    // A (a-values, 16KB) aliases 0..16384 after main loop.
    __shared__ __align__(16) char smem[43648];
    float4* X4 = (float4*)smem;
    float4* W4 = (float4*)(smem + 8192);
    float*  X2 = (float*)(smem + 43008);
    float*  W2 = (float*)(smem + 43136);
    float*  A  = (float*)smem;
    float4* A4 = (float4*)smem;

    const int t = threadIdx.x;
    const int lane = t & 31;
    const int row0 = blockIdx.x * BROWS;

    // stage x tile (512 f4) + per-row |x|^2 via width-16 reduction
    {
        const float4* src = (const float4*)(data + row0 * D);
#pragma unroll
        for (int m = 0; m < 2; m++) {
            int i = t + 256 * m;                  // f4 index; row = i>>4
            float4 v = src[i];
            X4[i] = v;
            float p = fmaf(v.x, v.x, fmaf(v.y, v.y, fmaf(v.z, v.z, v.w * v.w)));
#pragma unroll
            for (int o = 8; o; o >>= 1) p += __shfl_down_sync(0xFFFFFFFFu, p, o, 16);
            if ((t & 15) == 0) X2[(t >> 4) + 16 * m] = p;
        }
    }
    // stage w tile (2048 f4, padded [col*17+c]) + per-col |w|^2
    {
        const float4* src = (const float4*)weights;
#pragma unroll
        for (int m = 0; m < 8; m++) {
            int i = t + 256 * m;
            int col = i >> 4, c = i & 15;
            float4 v = src[i];
            W4[col * 17 + c] = v;
            float p = fmaf(v.x, v.x, fmaf(v.y, v.y, fmaf(v.z, v.z, v.w * v.w)));
#pragma unroll
            for (int o = 8; o; o >>= 1) p += __shfl_down_sync(0xFFFFFFFFu, p, o, 16);
            if ((t & 15) == 0) W2[col] = p;
        }
    }
    __syncthreads();

    // main GEMM loop: warp owns rows 4*wr..4*wr+3; lane owns cols lane+32j
    const int wr = t >> 5;
    float acc[4][4] = {};
#pragma unroll
    for (int c = 0; c < 16; c++) {
        float4 xr[4], wv[4];
#pragma unroll
        for (int i = 0; i < 4; i++) xr[i] = X4[(4 * wr + i) * 16 + c];   // broadcast
#pragma unroll
        for (int j = 0; j < 4; j++) wv[j] = W4[(lane + 32 * j) * 17 + c];
#pragma unroll
        for (int i = 0; i < 4; i++)
#pragma unroll
            for (int j = 0; j < 4; j++) {
                acc[i][j] = fmaf(xr[i].x, wv[j].x, acc[i][j]);
                acc[i][j] = fmaf(xr[i].y, wv[j].y, acc[i][j]);
                acc[i][j] = fmaf(xr[i].z, wv[j].z, acc[i][j]);
                acc[i][j] = fmaf(xr[i].w, wv[j].w, acc[i][j]);
            }
    }
    __syncthreads();            // X/W reads done; A may overwrite

    // epilogue: dist -> gmem, a -> smem A
#pragma unroll
    for (int i = 0; i < 4; i++) {
        int rl = 4 * wr + i;
        float x2v = X2[rl];
#pragma unroll
        for (int j = 0; j < 4; j++) {
            int col = lane + 32 * j;
            float d2 = fmaf(-2.0f, acc[i][j], x2v + W2[col]);
            float dd = fsqrt_(fmaxf(d2, 0.0f));
            g_dist[(row0 + rl) * K + col] = dd;
            A[rl * K + col] = fex2(fmaf(dd, 5.0f * LOG2E, -20.0f * LOG2E));
        }
    }
    __syncthreads();

    // symmetric polys: 1024 (row,group) tasks, 4 per thread
#pragma unroll
    for (int m = 0; m < 4; m++) {
        int task = t + 256 * m;
        int r = task >> 5, g = task & 31;
        float4 b = A4[r * 32 + g];
        float s12 = b.x + b.y, p12 = b.x * b.y;
        float s34 = b.z + b.w, p34 = b.z * b.w;
        float4 e;
        e.x = s12 + s34;
        e.y = fmaf(s12, s34, p12 + p34);
        e.z = fmaf(p12, s34, p34 * s12);
        e.w = p12 * p34;
        g_E[(row0 + r) * (K / 4) + g] = e;
    }
}

// ---------- Kernel B: rank phase (unchanged from R10; 47.5us proven) ----------
__global__ __launch_bounds__(256) void rankB(float* __restrict__ out)
{
    __shared__ float4 E_s[RB][K / 4];
    __shared__ float warp_sums[8];

    const int t = threadIdx.x;
    const int rloc = t >> 6;
    const int tk = t & 63;
    const int lane = t & 31;
    const int wid = t >> 5;
    const int row0 = blockIdx.x * RB;

    if (t < RB * (K / 4))
        ((float4*)E_s)[t] = g_E[row0 * (K / 4) + t];

    const int row = row0 + rloc;
    float d1 = g_dist[row * K + tk];
    float d2 = g_dist[row * K + tk + 64];
    __syncthreads();

    const float a1 = fex2(fmaf(d1, 5.0f * LOG2E, -20.0f * LOG2E));
    const float a2 = fex2(fmaf(d2, 5.0f * LOG2E, -20.0f * LOG2E));
    float q1 = 0.0f, q2 = 0.0f;
#pragma unroll
    for (int g = 0; g < K / 4; g++) {
        float4 E = E_s[rloc][g];
        {
            float h1 = a1 + E.x;
            float h2 = fmaf(h1, a1, E.y);
            float h3 = fmaf(h2, a1, E.z);
            float P  = fmaf(h3, a1, E.w);
            float g2 = h1 + a1;
            float g3 = fmaf(g2, a1, h2);
            float N  = fmaf(g3, a1, h3);
            q1 = fmaf(N, frcp(P), q1);
        }
        {
            float h1 = a2 + E.x;
            float h2 = fmaf(h1, a2, E.y);
            float h3 = fmaf(h2, a2, E.z);
            float P  = fmaf(h3, a2, E.w);
            float g2 = h1 + a2;
            float g3 = fmaf(g2, a2, h2);
            float N  = fmaf(g3, a2, h3);
            q2 = fmaf(N, frcp(P), q2);
        }
    }
    float rk1 = fmaf(a1, q1, -0.5f);
    float rk2 = fmaf(a2, q2, -0.5f);
    float acc = fmaf(fex2(-rk1 * (0.125f * LOG2E)), d1,
                     fex2(-rk2 * (0.125f * LOG2E)) * d2);

#pragma unroll
    for (int o = 16; o; o >>= 1) acc += __shfl_down_sync(0xFFFFFFFFu, acc, o);
    if (lane == 0) warp_sums[wid] = acc;
    __syncthreads();
    if (t == 0) {
        float s = 0.0f;
#pragma unroll
        for (int i = 0; i < 8; i++) s += warp_sums[i];
        atomicAdd(out, s * (1.0f / ((float)NROWS * (float)K)));
    }
}

extern "C" void kernel_launch(void* const* d_in, const int* in_sizes, int n_in,
                              void* d_out, int out_size)
{
    const float* data    = (const float*)d_in[0];
    const float* weights = (const float*)d_in[1];
    float* out = (float*)d_out;

    cudaMemsetAsync(out, 0, sizeof(float));
    distA<<<NBLOCKS_A, 256>>>(data, weights);
    rankB<<<NBLOCKS_B, 256>>>(out);
}

// round 12
// speedup vs baseline: 1.3242x; 1.0714x over previous
#include <cuda_runtime.h>

#define NROWS 16384
#define K 128
#define D 64
#define BROWS 32
#define NBLOCKS_A (NROWS / BROWS)
#define RB 8
#define NBLOCKS_B (NROWS / RB)
#define LOG2E 1.4426950408889634f

__device__ __forceinline__ float frcp(float x) {
    float r; asm("rcp.approx.f32 %0, %1;" : "=f"(r) : "f"(x)); return r;
}
__device__ __forceinline__ float fex2(float x) {
    float r; asm("ex2.approx.f32 %0, %1;" : "=f"(r) : "f"(x)); return r;
}
__device__ __forceinline__ float fsqrt_(float x) {
    float r; asm("sqrt.approx.f32 %0, %1;" : "=f"(r) : "f"(x)); return r;
}

// Scratch (__device__ globals: the sanctioned no-alloc path)
__device__ float  g_dist[NROWS * K];      // 8 MB
__device__ float4 g_E[NROWS * (K / 4)];   // 8 MB

// loss = mean_{n,k} exp(-(rank_k-1)/8) * d_k
// rank_k-1 = (sum_all_j a/(a+a_j)) - 0.5,  a = exp(5d-20) (rescaled; ratios invariant)
// Group-of-4: P(a)=prod(a+b_i) Horner on symmetric polys e1..e4; N=P'; sum = a*N*rcp(P).

// ---------- Kernel A: GEMM-tiled distances + a + symmetric polys ----------
__global__ __launch_bounds__(256) void distA(const float* __restrict__ data,
                                             const float* __restrict__ weights)
{
    // layout: X 0..8192 | W 8192..43008 (f4 [col*17+c]) | X2 43008 | W2 43136..43648
    // A (a-values, 16KB) aliases 0..16384 after main loop.
    __shared__ __align__(16) char smem[43648];
    float4* X4 = (float4*)smem;
    float4* W4 = (float4*)(smem + 8192);
    float*  X2 = (float*)(smem + 43008);
    float*  W2 = (float*)(smem + 43136);
    float*  A  = (float*)smem;
    float4* A4 = (float4*)smem;

    const int t = threadIdx.x;
    const int lane = t & 31;
    const int row0 = blockIdx.x * BROWS;

    // stage x tile (512 f4) + per-row |x|^2 via width-16 reduction
    {
        const float4* src = (const float4*)(data + row0 * D);
#pragma unroll
        for (int m = 0; m < 2; m++) {
            int i = t + 256 * m;                  // f4 index; row = i>>4
            float4 v = src[i];
            X4[i] = v;
            float p = fmaf(v.x, v.x, fmaf(v.y, v.y, fmaf(v.z, v.z, v.w * v.w)));
#pragma unroll
            for (int o = 8; o; o >>= 1) p += __shfl_down_sync(0xFFFFFFFFu, p, o, 16);
            if ((t & 15) == 0) X2[(t >> 4) + 16 * m] = p;
        }
    }
    // stage w tile (2048 f4, padded [col*17+c]) + per-col |w|^2
    {
        const float4* src = (const float4*)weights;
#pragma unroll
        for (int m = 0; m < 8; m++) {
            int i = t + 256 * m;
            int col = i >> 4, c = i & 15;
            float4 v = src[i];
            W4[col * 17 + c] = v;
            float p = fmaf(v.x, v.x, fmaf(v.y, v.y, fmaf(v.z, v.z, v.w * v.w)));
#pragma unroll
            for (int o = 8; o; o >>= 1) p += __shfl_down_sync(0xFFFFFFFFu, p, o, 16);
            if ((t & 15) == 0) W2[col] = p;
        }
    }
    __syncthreads();

    // main GEMM loop: warp owns rows 4*wr..4*wr+3; lane owns cols lane+32j
    const int wr = t >> 5;
    float acc[4][4] = {};
#pragma unroll
    for (int c = 0; c < 16; c++) {
        float4 xr[4], wv[4];
#pragma unroll
        for (int i = 0; i < 4; i++) xr[i] = X4[(4 * wr + i) * 16 + c];   // broadcast
#pragma unroll
        for (int j = 0; j < 4; j++) wv[j] = W4[(lane + 32 * j) * 17 + c];
#pragma unroll
        for (int i = 0; i < 4; i++)
#pragma unroll
            for (int j = 0; j < 4; j++) {
                acc[i][j] = fmaf(xr[i].x, wv[j].x, acc[i][j]);
                acc[i][j] = fmaf(xr[i].y, wv[j].y, acc[i][j]);
                acc[i][j] = fmaf(xr[i].z, wv[j].z, acc[i][j]);
                acc[i][j] = fmaf(xr[i].w, wv[j].w, acc[i][j]);
            }
    }
    __syncthreads();            // X/W reads done; A may overwrite

    // epilogue: dist -> gmem, a -> smem A
#pragma unroll
    for (int i = 0; i < 4; i++) {
        int rl = 4 * wr + i;
        float x2v = X2[rl];
#pragma unroll
        for (int j = 0; j < 4; j++) {
            int col = lane + 32 * j;
            float d2 = fmaf(-2.0f, acc[i][j], x2v + W2[col]);
            float dd = fsqrt_(fmaxf(d2, 0.0f));
            g_dist[(row0 + rl) * K + col] = dd;
            A[rl * K + col] = fex2(fmaf(dd, 5.0f * LOG2E, -20.0f * LOG2E));
        }
    }
    __syncthreads();

    // symmetric polys: 1024 (row,group) tasks, 4 per thread
#pragma unroll
    for (int m = 0; m < 4; m++) {
        int task = t + 256 * m;
        int r = task >> 5, g = task & 31;
        float4 b = A4[r * 32 + g];
        float s12 = b.x + b.y, p12 = b.x * b.y;
        float s34 = b.z + b.w, p34 = b.z * b.w;
        float4 e;
        e.x = s12 + s34;
        e.y = fmaf(s12, s34, p12 + p34);
        e.z = fmaf(p12, s34, p34 * s12);
        e.w = p12 * p34;
        g_E[(row0 + r) * (K / 4) + g] = e;
    }
}

// ---------- Kernel B: rank phase — warp-per-row, 4 centroids/thread ----------
__global__ __launch_bounds__(256) void rankB(float* __restrict__ out)
{
    __shared__ float4 E_s[RB][K / 4];       // 8 rows x 32 groups
    __shared__ float warp_sums[8];

    const int t = threadIdx.x;
    const int lane = t & 31;
    const int wid = t >> 5;                 // warp = local row
    const int row0 = blockIdx.x * RB;
    const int row = row0 + wid;

    // stage E: 256 float4, one per thread, coalesced
    ((float4*)E_s)[t] = g_E[row0 * (K / 4) + t];

    // this thread's 4 centroids: lane + 32m
    float d[4], a[4];
#pragma unroll
    for (int m = 0; m < 4; m++)
        d[m] = g_dist[row * K + lane + 32 * m];
    __syncthreads();

#pragma unroll
    for (int m = 0; m < 4; m++)
        a[m] = fex2(fmaf(d[m], 5.0f * LOG2E, -20.0f * LOG2E));

    float q[4] = {};
#pragma unroll
    for (int g = 0; g < K / 4; g++) {
        float4 E = E_s[wid][g];             // warp-uniform broadcast
#pragma unroll
        for (int m = 0; m < 4; m++) {       // 4 independent chains
            float h1 = a[m] + E.x;
            float h2 = fmaf(h1, a[m], E.y);
            float h3 = fmaf(h2, a[m], E.z);
            float P  = fmaf(h3, a[m], E.w);
            float g2 = h1 + a[m];
            float g3 = fmaf(g2, a[m], h2);
            float N  = fmaf(g3, a[m], h3);
            q[m] = fmaf(N, frcp(P), q[m]);
        }
    }

    float acc = 0.0f;
#pragma unroll
    for (int m = 0; m < 4; m++) {
        float rk = fmaf(a[m], q[m], -0.5f);
        acc = fmaf(fex2(-rk * (0.125f * LOG2E)), d[m], acc);
    }

    // block reduction -> atomic
#pragma unroll
    for (int o = 16; o; o >>= 1) acc += __shfl_down_sync(0xFFFFFFFFu, acc, o);
    if (lane == 0) warp_sums[wid] = acc;
    __syncthreads();
    if (t == 0) {
        float s = 0.0f;
#pragma unroll
        for (int i = 0; i < 8; i++) s += warp_sums[i];
        atomicAdd(out, s * (1.0f / ((float)NROWS * (float)K)));
    }
}

extern "C" void kernel_launch(void* const* d_in, const int* in_sizes, int n_in,
                              void* d_out, int out_size)
{
    const float* data    = (const float*)d_in[0];
    const float* weights = (const float*)d_in[1];
    float* out = (float*)d_out;

    cudaMemsetAsync(out, 0, sizeof(float));
    distA<<<NBLOCKS_A, 256>>>(data, weights);
    rankB<<<NBLOCKS_B, 256>>>(out);
}

// round 13
// speedup vs baseline: 1.9387x; 1.4641x over previous
#include <cuda_runtime.h>

#define NROWS 16384
#define K 128
#define D 64
#define BROWS 32
#define NBLOCKS_A (NROWS / BROWS)
#define RB 8
#define NBLOCKS_B (NROWS / RB)
#define LOG2E 1.4426950408889634f
#define PI_F 3.14159265358979f
#define NNODE 32
#define CHEB_M 24

__device__ __forceinline__ float frcp(float x) {
    float r; asm("rcp.approx.f32 %0, %1;" : "=f"(r) : "f"(x)); return r;
}
__device__ __forceinline__ float fex2(float x) {
    float r; asm("ex2.approx.f32 %0, %1;" : "=f"(r) : "f"(x)); return r;
}
__device__ __forceinline__ float fsqrt_(float x) {
    float r; asm("sqrt.approx.f32 %0, %1;" : "=f"(r) : "f"(x)); return r;
}

// Scratch (__device__ globals: the sanctioned no-alloc path)
__device__ float  g_dist[NROWS * K];      // 8 MB
__device__ float4 g_E[NROWS * (K / 4)];   // 8 MB

// loss = mean_{n,k} exp(-(rank_k-1)/8) * d_k
// rank_k-1 = f(d_k) - 0.5,  f(t) = sum_j a(t)/(a(t)+a_j),  a = exp(5d-20)
// Exact f via group-of-4 symmetric polys (P Horner, N=P' chain, 1 RCP/4 pairs).
// rankB: f is smooth per row -> evaluate exactly at 32 Chebyshev nodes,
// DCT -> 24 coefficients -> Clenshaw at the 128 query distances.

// ---------- Kernel A: GEMM-tiled distances + a + symmetric polys ----------
__global__ __launch_bounds__(256) void distA(const float* __restrict__ data,
                                             const float* __restrict__ weights)
{
    // layout: X 0..8192 | W 8192..43008 (f4 [col*17+c]) | X2 43008 | W2 43136..43648
    // A (a-values, 16KB) aliases 0..16384 after main loop.
    __shared__ __align__(16) char smem[43648];
    float4* X4 = (float4*)smem;
    float4* W4 = (float4*)(smem + 8192);
    float*  X2 = (float*)(smem + 43008);
    float*  W2 = (float*)(smem + 43136);
    float*  A  = (float*)smem;
    float4* A4 = (float4*)smem;

    const int t = threadIdx.x;
    const int lane = t & 31;
    const int row0 = blockIdx.x * BROWS;

    {
        const float4* src = (const float4*)(data + row0 * D);
#pragma unroll
        for (int m = 0; m < 2; m++) {
            int i = t + 256 * m;
            float4 v = src[i];
            X4[i] = v;
            float p = fmaf(v.x, v.x, fmaf(v.y, v.y, fmaf(v.z, v.z, v.w * v.w)));
#pragma unroll
            for (int o = 8; o; o >>= 1) p += __shfl_down_sync(0xFFFFFFFFu, p, o, 16);
            if ((t & 15) == 0) X2[(t >> 4) + 16 * m] = p;
        }
    }
    {
        const float4* src = (const float4*)weights;
#pragma unroll
        for (int m = 0; m < 8; m++) {
            int i = t + 256 * m;
            int col = i >> 4, c = i & 15;
            float4 v = src[i];
            W4[col * 17 + c] = v;
            float p = fmaf(v.x, v.x, fmaf(v.y, v.y, fmaf(v.z, v.z, v.w * v.w)));
#pragma unroll
            for (int o = 8; o; o >>= 1) p += __shfl_down_sync(0xFFFFFFFFu, p, o, 16);
            if ((t & 15) == 0) W2[col] = p;
        }
    }
    __syncthreads();

    const int wr = t >> 5;
    float acc[4][4] = {};
#pragma unroll
    for (int c = 0; c < 16; c++) {
        float4 xr[4], wv[4];
#pragma unroll
        for (int i = 0; i < 4; i++) xr[i] = X4[(4 * wr + i) * 16 + c];
#pragma unroll
        for (int j = 0; j < 4; j++) wv[j] = W4[(lane + 32 * j) * 17 + c];
#pragma unroll
        for (int i = 0; i < 4; i++)
#pragma unroll
            for (int j = 0; j < 4; j++) {
                acc[i][j] = fmaf(xr[i].x, wv[j].x, acc[i][j]);
                acc[i][j] = fmaf(xr[i].y, wv[j].y, acc[i][j]);
                acc[i][j] = fmaf(xr[i].z, wv[j].z, acc[i][j]);
                acc[i][j] = fmaf(xr[i].w, wv[j].w, acc[i][j]);
            }
    }
    __syncthreads();

#pragma unroll
    for (int i = 0; i < 4; i++) {
        int rl = 4 * wr + i;
        float x2v = X2[rl];
#pragma unroll
        for (int j = 0; j < 4; j++) {
            int col = lane + 32 * j;
            float d2 = fmaf(-2.0f, acc[i][j], x2v + W2[col]);
            float dd = fsqrt_(fmaxf(d2, 0.0f));
            g_dist[(row0 + rl) * K + col] = dd;
            A[rl * K + col] = fex2(fmaf(dd, 5.0f * LOG2E, -20.0f * LOG2E));
        }
    }
    __syncthreads();

#pragma unroll
    for (int m = 0; m < 4; m++) {
        int task = t + 256 * m;
        int r = task >> 5, g = task & 31;
        float4 b = A4[r * 32 + g];
        float s12 = b.x + b.y, p12 = b.x * b.y;
        float s34 = b.z + b.w, p34 = b.z * b.w;
        float4 e;
        e.x = s12 + s34;
        e.y = fmaf(s12, s34, p12 + p34);
        e.z = fmaf(p12, s34, p34 * s12);
        e.w = p12 * p34;
        g_E[(row0 + r) * (K / 4) + g] = e;
    }
}

// ---------- Kernel B: rank via 32-node Chebyshev fit per row ----------
__global__ __launch_bounds__(256) void rankB(float* __restrict__ out)
{
    __shared__ float4 E_s[RB][K / 4];
    __shared__ float cosT[NNODE * 33];       // [m*33+i] = cos(m*(i+0.5)*pi/32), padded
    __shared__ float warp_sums[8];

    const int t = threadIdx.x;
    const int lane = t & 31;
    const int wid = t >> 5;                  // warp = local row
    const int row0 = blockIdx.x * RB;
    const int row = row0 + wid;

    // cos table via exact integer mod-128 range reduction (|arg| <= 2*pi)
    for (int idx = t; idx < NNODE * 33; idx += 256) {
        int m = idx / 33, i = idx - m * 33;
        if (i < 32) {
            int r = (m * (2 * i + 1)) & 127;
            cosT[idx] = __cosf((float)r * (PI_F / 64.0f));
        }
    }
    ((float4*)E_s)[t] = g_E[row0 * (K / 4) + t];
    float d[4];
#pragma unroll
    for (int m = 0; m < 4; m++)
        d[m] = g_dist[row * K + lane + 32 * m];
    __syncthreads();

    // per-row distance range
    float lmin = fminf(fminf(d[0], d[1]), fminf(d[2], d[3]));
    float lmax = fmaxf(fmaxf(d[0], d[1]), fmaxf(d[2], d[3]));
#pragma unroll
    for (int o = 16; o; o >>= 1) {
        lmin = fminf(lmin, __shfl_xor_sync(0xFFFFFFFFu, lmin, o));
        lmax = fmaxf(lmax, __shfl_xor_sync(0xFFFFFFFFu, lmax, o));
    }
    const float mid = 0.5f * (lmin + lmax);
    const float rad = fmaxf(0.5f * (lmax - lmin), 1e-5f);
    const float irad = frcp(rad);

    // exact f at node lane: t_i = mid + rad*cos(theta_i)
    const float tn = fmaf(rad, cosT[33 + lane], mid);   // row m=1 of table = cos(theta_i)
    const float Av = fex2(fmaf(tn, 5.0f * LOG2E, -20.0f * LOG2E));
    float q = 0.0f;
#pragma unroll
    for (int g = 0; g < K / 4; g++) {
        float4 E = E_s[wid][g];              // warp-uniform broadcast
        float h1 = Av + E.x;
        float h2 = fmaf(h1, Av, E.y);
        float h3 = fmaf(h2, Av, E.z);
        float P  = fmaf(h3, Av, E.w);
        float g2 = h1 + Av;
        float g3 = fmaf(g2, Av, h2);
        float N  = fmaf(g3, Av, h3);
        q = fmaf(N, frcp(P), q);
    }
    const float fn = fmaf(Av, q, -64.0f);    // centered f(t_lane)

    // 32-pt DCT: lane computes coefficient c_lane
    float c = 0.0f;
#pragma unroll
    for (int i = 0; i < NNODE; i++) {
        float fv = __shfl_sync(0xFFFFFFFFu, fn, i);
        c = fmaf(fv, cosT[lane * 33 + i], c);   // bank = (lane+i)%32, conflict-free
    }
    c *= (2.0f / NNODE);

    // Clenshaw, 24 terms, 4 query points per lane
    const float c0h = 0.5f * __shfl_sync(0xFFFFFFFFu, c, 0);
    float y[4], y2[4], b1[4] = {}, b2[4] = {};
#pragma unroll
    for (int m = 0; m < 4; m++) {
        y[m] = (d[m] - mid) * irad;
        y2[m] = 2.0f * y[m];
    }
#pragma unroll
    for (int mm = CHEB_M - 1; mm >= 1; mm--) {
        float cm = __shfl_sync(0xFFFFFFFFu, c, mm);
#pragma unroll
        for (int m = 0; m < 4; m++) {
            float bn = fmaf(y2[m], b1[m], cm - b2[m]);
            b2[m] = b1[m]; b1[m] = bn;
        }
    }
    float acc = 0.0f;
#pragma unroll
    for (int m = 0; m < 4; m++) {
        float p = fmaf(y[m], b1[m], c0h - b2[m]);
        float rk = p + 63.5f;                // +64 recenter, -0.5 diagonal
        acc = fmaf(fex2(-rk * (0.125f * LOG2E)), d[m], acc);
    }

    // block reduction -> atomic
#pragma unroll
    for (int o = 16; o; o >>= 1) acc += __shfl_down_sync(0xFFFFFFFFu, acc, o);
    if (lane == 0) warp_sums[wid] = acc;
    __syncthreads();
    if (t == 0) {
        float s = 0.0f;
#pragma unroll
        for (int i = 0; i < 8; i++) s += warp_sums[i];
        atomicAdd(out, s * (1.0f / ((float)NROWS * (float)K)));
    }
}

extern "C" void kernel_launch(void* const* d_in, const int* in_sizes, int n_in,
                              void* d_out, int out_size)
{
    const float* data    = (const float*)d_in[0];
    const float* weights = (const float*)d_in[1];
    float* out = (float*)d_out;

    cudaMemsetAsync(out, 0, sizeof(float));
    distA<<<NBLOCKS_A, 256>>>(data, weights);
    rankB<<<NBLOCKS_B, 256>>>(out);
}

// round 15
// speedup vs baseline: 2.3106x; 1.1918x over previous
#include <cuda_runtime.h>

#define NROWS 16384
#define K 128
#define D 64
#define BROWS 32
#define NBLOCKS_A (NROWS / BROWS)
#define RB 8
#define NBLOCKS_B (NROWS / RB)
#define LOG2E 1.4426950408889634f
#define PI_F 3.14159265358979f
#define NNODE 16
#define CHEB_M 16

__device__ __forceinline__ float frcp(float x) {
    float r; asm("rcp.approx.f32 %0, %1;" : "=f"(r) : "f"(x)); return r;
}
__device__ __forceinline__ float fex2(float x) {
    float r; asm("ex2.approx.f32 %0, %1;" : "=f"(r) : "f"(x)); return r;
}
__device__ __forceinline__ float fsqrt_(float x) {
    float r; asm("sqrt.approx.f32 %0, %1;" : "=f"(r) : "f"(x)); return r;
}

// Scratch (__device__ globals: the sanctioned no-alloc path)
__device__ float  g_dist[NROWS * K];      // 8 MB
__device__ float4 g_E[NROWS * (K / 4)];   // 8 MB

// loss = mean_{n,k} exp(-(rank_k-1)/8) * d_k
// rank_k-1 = f(d_k) - 0.5,  f(t) = sum_j a(t)/(a(t)+a_j),  a = exp(5t-20)
// Exact f via group-of-4 symmetric polys (Horner P, N=P', 1 RCP / 4 pairs).
// rankB: f smooth per row -> exact f at 16 Chebyshev nodes (node split across
// lane pairs), 16-coeff DCT, Clenshaw at the 128 query distances.

// ---------- Kernel A: GEMM-tiled distances + a + symmetric polys ----------
__global__ __launch_bounds__(256) void distA(const float* __restrict__ data,
                                             const float* __restrict__ weights)
{
    // layout: X 0..8192 | W 8192..41984 (f4 [c*132+col]) | X2 41984 | W2 42112..42624
    // A (16KB) aliases 0..16384 after main loop (X + low W rows; neither read later).
    __shared__ __align__(16) char smem[42624];
    float4* X4 = (float4*)smem;
    float4* W4 = (float4*)(smem + 8192);
    float*  X2 = (float*)(smem + 41984);
    float*  W2 = (float*)(smem + 42112);
    float*  A  = (float*)smem;
    float4* A4 = (float4*)smem;

    const int t = threadIdx.x;
    const int lane = t & 31;
    const int row0 = blockIdx.x * BROWS;

    // stage x tile (512 f4) + per-row |x|^2
    {
        const float4* src = (const float4*)(data + row0 * D);
#pragma unroll
        for (int m = 0; m < 2; m++) {
            int i = t + 256 * m;                  // row = i>>4
            float4 v = src[i];
            X4[i] = v;
            float p = fmaf(v.x, v.x, fmaf(v.y, v.y, fmaf(v.z, v.z, v.w * v.w)));
#pragma unroll
            for (int o = 8; o; o >>= 1) p += __shfl_down_sync(0xFFFFFFFFu, p, o, 16);
            if ((t & 15) == 0) X2[(t >> 4) + 16 * m] = p;
        }
    }
    // stage w tile transposed: W4[c*132 + col]  (lane-consecutive cols in main loop)
    {
        const float4* src = (const float4*)weights;
#pragma unroll
        for (int m = 0; m < 8; m++) {
            int i = t + 256 * m;
            int col = i >> 4, c = i & 15;
            float4 v = src[i];
            W4[c * 132 + col] = v;
            float p = fmaf(v.x, v.x, fmaf(v.y, v.y, fmaf(v.z, v.z, v.w * v.w)));
#pragma unroll
            for (int o = 8; o; o >>= 1) p += __shfl_down_sync(0xFFFFFFFFu, p, o, 16);
            if ((t & 15) == 0) W2[col] = p;
        }
    }
    __syncthreads();

    // main GEMM: warp owns rows 4*wr..4*wr+3; lane owns cols lane+32j
    const int wr = t >> 5;
    float acc[4][4] = {};
#pragma unroll
    for (int c = 0; c < 16; c++) {
        float4 xr[4], wv[4];
#pragma unroll
        for (int i = 0; i < 4; i++) xr[i] = X4[(4 * wr + i) * 16 + c];   // broadcast
#pragma unroll
        for (int j = 0; j < 4; j++) wv[j] = W4[c * 132 + lane + 32 * j]; // conflict-free
#pragma unroll
        for (int i = 0; i < 4; i++)
#pragma unroll
            for (int j = 0; j < 4; j++) {
                acc[i][j] = fmaf(xr[i].x, wv[j].x, acc[i][j]);
                acc[i][j] = fmaf(xr[i].y, wv[j].y, acc[i][j]);
                acc[i][j] = fmaf(xr[i].z, wv[j].z, acc[i][j]);
                acc[i][j] = fmaf(xr[i].w, wv[j].w, acc[i][j]);
            }
    }
    __syncthreads();            // X/W reads done; A may overwrite

    // epilogue: dist -> gmem, a -> smem A
#pragma unroll
    for (int i = 0; i < 4; i++) {
        int rl = 4 * wr + i;
        float x2v = X2[rl];
#pragma unroll
        for (int j = 0; j < 4; j++) {
            int col = lane + 32 * j;
            float d2 = fmaf(-2.0f, acc[i][j], x2v + W2[col]);
            float dd = fsqrt_(fmaxf(d2, 0.0f));
            g_dist[(row0 + rl) * K + col] = dd;
            A[rl * K + col] = fex2(fmaf(dd, 5.0f * LOG2E, -20.0f * LOG2E));
        }
    }
    __syncthreads();

    // symmetric polys: 1024 (row,group) tasks, 4 per thread
#pragma unroll
    for (int m = 0; m < 4; m++) {
        int task = t + 256 * m;
        int r = task >> 5, g = task & 31;
        float4 b = A4[r * 32 + g];
        float s12 = b.x + b.y, p12 = b.x * b.y;
        float s34 = b.z + b.w, p34 = b.z * b.w;
        float4 e;
        e.x = s12 + s34;
        e.y = fmaf(s12, s34, p12 + p34);
        e.z = fmaf(p12, s34, p34 * s12);
        e.w = p12 * p34;
        g_E[(row0 + r) * (K / 4) + g] = e;
    }
}

// ---------- Kernel B: rank via 16-node Chebyshev fit per row ----------
__global__ __launch_bounds__(256) void rankB(float* __restrict__ out)
{
    __shared__ float4 E_s[RB][K / 4];
    __shared__ float cosT[NNODE * 17];       // [m*17+i] = cos(m*(2i+1)*pi/32)
    __shared__ float warp_sums[8];

    const int t = threadIdx.x;
    const int lane = t & 31;
    const int wid = t >> 5;                  // warp = local row
    const int row0 = blockIdx.x * RB;
    const int row = row0 + wid;
    const int node = lane & 15;
    const int half = lane >> 4;

    // cos table: exact integer mod-64 range reduction.
    // GRID-STRIDE: NNODE*17 = 272 > 256 threads, must loop (R14 bug was `if`).
    for (int idx = t; idx < NNODE * 17; idx += 256) {
        int m = idx / 17, i = idx - m * 17;
        if (i < 16) {
            int r = (m * (2 * i + 1)) & 63;
            cosT[idx] = __cosf((float)r * (PI_F / 32.0f));
        }
    }
    ((float4*)E_s)[t] = g_E[row0 * (K / 4) + t];
    float d[4];
#pragma unroll
    for (int m = 0; m < 4; m++)
        d[m] = g_dist[row * K + lane + 32 * m];
    __syncthreads();

    // per-row distance range
    float lmin = fminf(fminf(d[0], d[1]), fminf(d[2], d[3]));
    float lmax = fmaxf(fmaxf(d[0], d[1]), fmaxf(d[2], d[3]));
#pragma unroll
    for (int o = 16; o; o >>= 1) {
        lmin = fminf(lmin, __shfl_xor_sync(0xFFFFFFFFu, lmin, o));
        lmax = fmaxf(lmax, __shfl_xor_sync(0xFFFFFFFFu, lmax, o));
    }
    const float mid = 0.5f * (lmin + lmax);
    const float rad = fmaxf(0.5f * (lmax - lmin), 1e-5f);
    const float irad = frcp(rad);

    // exact f at node (lane&15); lane pair (l, l+16) splits the 32 groups
    const float tn = fmaf(rad, cosT[17 + node], mid);    // m=1 row = cos(theta_i)
    const float Av = fex2(fmaf(tn, 5.0f * LOG2E, -20.0f * LOG2E));
    float q = 0.0f;
#pragma unroll
    for (int g = 0; g < 16; g++) {
        float4 E = E_s[wid][half * 16 + g];  // 2 addrs/warp -> broadcast pair
        float h1 = Av + E.x;
        float h2 = fmaf(h1, Av, E.y);
        float h3 = fmaf(h2, Av, E.z);
        float P  = fmaf(h3, Av, E.w);
        float g2 = h1 + Av;
        float g3 = fmaf(g2, Av, h2);
        float N  = fmaf(g3, Av, h3);
        q = fmaf(N, frcp(P), q);
    }
    q += __shfl_xor_sync(0xFFFFFFFFu, q, 16);
    const float fn = fmaf(Av, q, -64.0f);    // centered f(t_node); lanes i and i+16 agree

    // 16-pt DCT: lane (both halves) computes c_{lane&15}
    float c = 0.0f;
#pragma unroll
    for (int i = 0; i < NNODE; i++) {
        float fv = __shfl_sync(0xFFFFFFFFu, fn, i);      // source lane i holds f_i
        c = fmaf(fv, cosT[node * 17 + i], c);
    }
    c *= (2.0f / NNODE);

    // Clenshaw, 16 terms, 4 query points per lane
    const float c0h = 0.5f * __shfl_sync(0xFFFFFFFFu, c, 0);
    float y[4], y2[4], b1[4] = {}, b2[4] = {};
#pragma unroll
    for (int m = 0; m < 4; m++) {
        y[m] = (d[m] - mid) * irad;
        y2[m] = 2.0f * y[m];
    }
#pragma unroll
    for (int mm = CHEB_M - 1; mm >= 1; mm--) {
        float cm = __shfl_sync(0xFFFFFFFFu, c, mm);
#pragma unroll
        for (int m = 0; m < 4; m++) {
            float bn = fmaf(y2[m], b1[m], cm - b2[m]);
            b2[m] = b1[m]; b1[m] = bn;
        }
    }
    float acc = 0.0f;
#pragma unroll
    for (int m = 0; m < 4; m++) {
        float p = fmaf(y[m], b1[m], c0h - b2[m]);
        float rk = p + 63.5f;                // +64 recenter, -0.5 diagonal
        acc = fmaf(fex2(-rk * (0.125f * LOG2E)), d[m], acc);
    }

    // block reduction -> atomic
#pragma unroll
    for (int o = 16; o; o >>= 1) acc += __shfl_down_sync(0xFFFFFFFFu, acc, o);
    if (lane == 0) warp_sums[wid] = acc;
    __syncthreads();
    if (t == 0) {
        float s = 0.0f;
#pragma unroll
        for (int i = 0; i < 8; i++) s += warp_sums[i];
        atomicAdd(out, s * (1.0f / ((float)NROWS * (float)K)));
    }
}

extern "C" void kernel_launch(void* const* d_in, const int* in_sizes, int n_in,
                              void* d_out, int out_size)
{
    const float* data    = (const float*)d_in[0];
    const float* weights = (const float*)d_in[1];
    float* out = (float*)d_out;

    cudaMemsetAsync(out, 0, sizeof(float));
    distA<<<NBLOCKS_A, 256>>>(data, weights);
    rankB<<<NBLOCKS_B, 256>>>(out);
}

// round 16
// speedup vs baseline: 2.4239x; 1.0490x over previous
#include <cuda_runtime.h>

#define NROWS 16384
#define K 128
#define D 64
#define BROWS 32
#define NBLOCKS (NROWS / BROWS)
#define LOG2E 1.4426950408889634f
#define PI_F 3.14159265358979f
#define NNODE 16
#define CHEB_M 16

__device__ __forceinline__ float frcp(float x) {
    float r; asm("rcp.approx.f32 %0, %1;" : "=f"(r) : "f"(x)); return r;
}
__device__ __forceinline__ float fex2(float x) {
    float r; asm("ex2.approx.f32 %0, %1;" : "=f"(r) : "f"(x)); return r;
}
__device__ __forceinline__ float fsqrt_(float x) {
    float r; asm("sqrt.approx.f32 %0, %1;" : "=f"(r) : "f"(x)); return r;
}

// loss = mean_{n,k} exp(-(rank_k-1)/8) * d_k
// rank_k-1 = f(d_k) - 0.5,  f(t) = sum_j a(t)/(a(t)+a_j),  a = exp(5t-20)
// FUSED: per block of 32 rows — GEMM-tiled distances (smem), group-of-4
// symmetric polys (smem), then per-warp 16-node Chebyshev rank fit + Clenshaw.
// No scratch gmem at all.

__global__ __launch_bounds__(256) void dng_fused(const float* __restrict__ data,
                                                 const float* __restrict__ weights,
                                                 float* __restrict__ out)
{
    // [0,8192)      X tile (512 f4)           — dead after GEMM
    // [8192,41984)  W tile f4[c*132+col]      — rows c>=4 dead after GEMM
    // [41984,42112) X2;  [42112,42624) W2
    // [42624,43712) cosT (16*17 floats)
    // aliases after GEMM: DIST [0,16384), E [16384,32768)
    __shared__ __align__(16) char smem[43712];
    float4* X4   = (float4*)smem;
    float4* W4   = (float4*)(smem + 8192);
    float*  X2   = (float*)(smem + 41984);
    float*  W2   = (float*)(smem + 42112);
    float*  cosT = (float*)(smem + 42624);
    float*  DIST  = (float*)smem;
    float4* DIST4 = (float4*)smem;
    float4* E4   = (float4*)(smem + 16384);
    __shared__ float warp_sums[8];

    const int t = threadIdx.x;
    const int lane = t & 31;
    const int wid = t >> 5;
    const int row0 = blockIdx.x * BROWS;

    // ---- phase 1: cos table + stage X (+|x|^2) + stage W transposed (+|w|^2) ----
    for (int idx = t; idx < NNODE * 17; idx += 256) {   // grid-stride: 272 > 256
        int m = idx / 17, i = idx - m * 17;
        if (i < 16) {
            int r = (m * (2 * i + 1)) & 63;             // exact integer mod-64
            cosT[idx] = __cosf((float)r * (PI_F / 32.0f));
        }
    }
    {
        const float4* src = (const float4*)(data + row0 * D);
#pragma unroll
        for (int m = 0; m < 2; m++) {
            int i = t + 256 * m;                        // row = i>>4
            float4 v = src[i];
            X4[i] = v;
            float p = fmaf(v.x, v.x, fmaf(v.y, v.y, fmaf(v.z, v.z, v.w * v.w)));
#pragma unroll
            for (int o = 8; o; o >>= 1) p += __shfl_down_sync(0xFFFFFFFFu, p, o, 16);
            if ((t & 15) == 0) X2[(t >> 4) + 16 * m] = p;
        }
    }
    {
        const float4* src = (const float4*)weights;
#pragma unroll
        for (int m = 0; m < 8; m++) {
            int i = t + 256 * m;
            int col = i >> 4, c = i & 15;
            float4 v = src[i];
            W4[c * 132 + col] = v;
            float p = fmaf(v.x, v.x, fmaf(v.y, v.y, fmaf(v.z, v.z, v.w * v.w)));
#pragma unroll
            for (int o = 8; o; o >>= 1) p += __shfl_down_sync(0xFFFFFFFFu, p, o, 16);
            if ((t & 15) == 0) W2[col] = p;
        }
    }
    __syncthreads();

    // ---- phase 2: GEMM — warp owns rows 4*wid..4*wid+3; lane owns cols lane+32j ----
    float acc4[4][4] = {};
#pragma unroll
    for (int c = 0; c < 16; c++) {
        float4 xr[4], wv[4];
#pragma unroll
        for (int i = 0; i < 4; i++) xr[i] = X4[(4 * wid + i) * 16 + c];   // broadcast
#pragma unroll
        for (int j = 0; j < 4; j++) wv[j] = W4[c * 132 + lane + 32 * j];  // conflict-free
#pragma unroll
        for (int i = 0; i < 4; i++)
#pragma unroll
            for (int j = 0; j < 4; j++) {
                acc4[i][j] = fmaf(xr[i].x, wv[j].x, acc4[i][j]);
                acc4[i][j] = fmaf(xr[i].y, wv[j].y, acc4[i][j]);
                acc4[i][j] = fmaf(xr[i].z, wv[j].z, acc4[i][j]);
                acc4[i][j] = fmaf(xr[i].w, wv[j].w, acc4[i][j]);
            }
    }
    __syncthreads();            // X/W reads done; DIST may overwrite X region

    // ---- phase 3: epilogue — distances into smem DIST ----
#pragma unroll
    for (int i = 0; i < 4; i++) {
        int rl = 4 * wid + i;
        float x2v = X2[rl];
#pragma unroll
        for (int j = 0; j < 4; j++) {
            int col = lane + 32 * j;
            float d2 = fmaf(-2.0f, acc4[i][j], x2v + W2[col]);
            DIST[rl * K + col] = fsqrt_(fmaxf(d2, 0.0f));
        }
    }
    __syncthreads();

    // ---- phase 4: symmetric polys E from DIST (a = exp(5d-20)) ----
#pragma unroll
    for (int m = 0; m < 4; m++) {
        int task = t + 256 * m;                 // 1024 = 32 rows x 32 groups
        int r = task >> 5, g = task & 31;
        float4 dv = DIST4[r * 32 + g];
        float b1 = fex2(fmaf(dv.x, 5.0f * LOG2E, -20.0f * LOG2E));
        float b2 = fex2(fmaf(dv.y, 5.0f * LOG2E, -20.0f * LOG2E));
        float b3 = fex2(fmaf(dv.z, 5.0f * LOG2E, -20.0f * LOG2E));
        float b4 = fex2(fmaf(dv.w, 5.0f * LOG2E, -20.0f * LOG2E));
        float s12 = b1 + b2, p12 = b1 * b2;
        float s34 = b3 + b4, p34 = b3 * b4;
        float4 e;
        e.x = s12 + s34;
        e.y = fmaf(s12, s34, p12 + p34);
        e.z = fmaf(p12, s34, p34 * s12);
        e.w = p12 * p34;
        E4[r * 32 + g] = e;
    }
    __syncthreads();

    // ---- phase 5: rank — each warp runs 4 rows through the Chebyshev pipeline ----
    const int node = lane & 15;
    const int half = lane >> 4;
    float acc = 0.0f;
#pragma unroll
    for (int rr = 0; rr < 4; rr++) {
        const int r = 4 * wid + rr;
        float d[4];
#pragma unroll
        for (int m = 0; m < 4; m++) d[m] = DIST[r * K + lane + 32 * m];

        float lmin = fminf(fminf(d[0], d[1]), fminf(d[2], d[3]));
        float lmax = fmaxf(fmaxf(d[0], d[1]), fmaxf(d[2], d[3]));
#pragma unroll
        for (int o = 16; o; o >>= 1) {
            lmin = fminf(lmin, __shfl_xor_sync(0xFFFFFFFFu, lmin, o));
            lmax = fmaxf(lmax, __shfl_xor_sync(0xFFFFFFFFu, lmax, o));
        }
        const float mid = 0.5f * (lmin + lmax);
        const float rad = fmaxf(0.5f * (lmax - lmin), 1e-5f);
        const float irad = frcp(rad);

        // exact f at node (lane&15); lane pair (l, l+16) splits the 32 groups
        const float tn = fmaf(rad, cosT[17 + node], mid);
        const float Av = fex2(fmaf(tn, 5.0f * LOG2E, -20.0f * LOG2E));
        float q = 0.0f;
#pragma unroll
        for (int g = 0; g < 16; g++) {
            float4 E = E4[r * 32 + half * 16 + g];
            float h1 = Av + E.x;
            float h2 = fmaf(h1, Av, E.y);
            float h3 = fmaf(h2, Av, E.z);
            float P  = fmaf(h3, Av, E.w);
            float g2 = h1 + Av;
            float g3 = fmaf(g2, Av, h2);
            float N  = fmaf(g3, Av, h3);
            q = fmaf(N, frcp(P), q);
        }
        q += __shfl_xor_sync(0xFFFFFFFFu, q, 16);
        const float fn = fmaf(Av, q, -64.0f);       // centered f(t_node)

        // 16-pt DCT: lane computes c_{lane&15}
        float c = 0.0f;
#pragma unroll
        for (int i = 0; i < NNODE; i++) {
            float fv = __shfl_sync(0xFFFFFFFFu, fn, i);
            c = fmaf(fv, cosT[node * 17 + i], c);
        }
        c *= (2.0f / NNODE);

        // Clenshaw at the 4 query distances
        const float c0h = 0.5f * __shfl_sync(0xFFFFFFFFu, c, 0);
        float y[4], y2[4], b1[4] = {}, b2[4] = {};
#pragma unroll
        for (int m = 0; m < 4; m++) {
            y[m] = (d[m] - mid) * irad;
            y2[m] = 2.0f * y[m];
        }
#pragma unroll
        for (int mm = CHEB_M - 1; mm >= 1; mm--) {
            float cm = __shfl_sync(0xFFFFFFFFu, c, mm);
#pragma unroll
            for (int m = 0; m < 4; m++) {
                float bn = fmaf(y2[m], b1[m], cm - b2[m]);
                b2[m] = b1[m]; b1[m] = bn;
            }
        }
#pragma unroll
        for (int m = 0; m < 4; m++) {
            float p = fmaf(y[m], b1[m], c0h - b2[m]);
            float rk = p + 63.5f;                   // +64 recenter, -0.5 diagonal
            acc = fmaf(fex2(-rk * (0.125f * LOG2E)), d[m], acc);
        }
    }

    // ---- block reduction -> global atomic ----
#pragma unroll
    for (int o = 16; o; o >>= 1) acc += __shfl_down_sync(0xFFFFFFFFu, acc, o);
    if (lane == 0) warp_sums[wid] = acc;
    __syncthreads();
    if (t == 0) {
        float s = 0.0f;
#pragma unroll
        for (int i = 0; i < 8; i++) s += warp_sums[i];
        atomicAdd(out, s * (1.0f / ((float)NROWS * (float)K)));
    }
}

extern "C" void kernel_launch(void* const* d_in, const int* in_sizes, int n_in,
                              void* d_out, int out_size)
{
    const float* data    = (const float*)d_in[0];
    const float* weights = (const float*)d_in[1];
    float* out = (float*)d_out;

    cudaMemsetAsync(out, 0, sizeof(float));
    dng_fused<<<NBLOCKS, 256>>>(data, weights, out);
}

// round 17
// speedup vs baseline: 2.5138x; 1.0371x over previous
#include <cuda_runtime.h>

#define NROWS 16384
#define K 128
#define D 64
#define BROWS 32
#define NBLOCKS (NROWS / BROWS)
#define LOG2E 1.4426950408889634f
#define PI_F 3.14159265358979f
#define NNODE 16
#define CHEB_M 12

__device__ __forceinline__ float frcp(float x) {
    float r; asm("rcp.approx.f32 %0, %1;" : "=f"(r) : "f"(x)); return r;
}
__device__ __forceinline__ float fex2(float x) {
    float r; asm("ex2.approx.f32 %0, %1;" : "=f"(r) : "f"(x)); return r;
}
__device__ __forceinline__ float fsqrt_(float x) {
    float r; asm("sqrt.approx.f32 %0, %1;" : "=f"(r) : "f"(x)); return r;
}

// loss = mean_{n,k} exp(-(rank_k-1)/8) * d_k
// rank_k-1 = f(d_k) - 0.5,  f(t) = sum_j a(t)/(a(t)+a_j),  a = exp(5t-20)
// FUSED, warp-local after the GEMM: warp wid owns rows 4wid..4wid+3 through
// epilogue -> symmetric polys -> 16-node Chebyshev fit -> 12-coeff Clenshaw.
// Only 2 block-wide barriers (post-staging, post-GEMM).

__global__ __launch_bounds__(256) void dng_fused(const float* __restrict__ data,
                                                 const float* __restrict__ weights,
                                                 float* __restrict__ out)
{
    // [0,8192) X | [8192,41984) W f4[c*132+col] | [41984,42112) X2 | [42112,42624) W2
    // [42624,43712) cosT.  After the post-GEMM barrier: DIST [0,16384), E [16384,32768).
    __shared__ __align__(16) char smem[43712];
    float4* X4   = (float4*)smem;
    float4* W4   = (float4*)(smem + 8192);
    float*  X2   = (float*)(smem + 41984);
    float*  W2   = (float*)(smem + 42112);
    float*  cosT = (float*)(smem + 42624);
    float*  DIST  = (float*)smem;
    float4* DIST4 = (float4*)smem;
    float4* E4   = (float4*)(smem + 16384);
    __shared__ float warp_sums[8];

    const int t = threadIdx.x;
    const int lane = t & 31;
    const int wid = t >> 5;
    const int row0 = blockIdx.x * BROWS;

    // ---- phase 1: cos table + stage X (+|x|^2) + stage W transposed (+|w|^2) ----
    for (int idx = t; idx < NNODE * 17; idx += 256) {   // grid-stride: 272 > 256
        int m = idx / 17, i = idx - m * 17;
        if (i < 16) {
            int r = (m * (2 * i + 1)) & 63;             // exact integer mod-64
            cosT[idx] = __cosf((float)r * (PI_F / 32.0f));
        }
    }
    {
        const float4* src = (const float4*)(data + row0 * D);
#pragma unroll
        for (int m = 0; m < 2; m++) {
            int i = t + 256 * m;                        // row = i>>4
            float4 v = src[i];
            X4[i] = v;
            float p = fmaf(v.x, v.x, fmaf(v.y, v.y, fmaf(v.z, v.z, v.w * v.w)));
#pragma unroll
            for (int o = 8; o; o >>= 1) p += __shfl_down_sync(0xFFFFFFFFu, p, o, 16);
            if ((t & 15) == 0) X2[(t >> 4) + 16 * m] = p;
        }
    }
    {
        const float4* src = (const float4*)weights;
#pragma unroll
        for (int m = 0; m < 8; m++) {
            int i = t + 256 * m;
            int col = i >> 4, c = i & 15;
            float4 v = src[i];
            W4[c * 132 + col] = v;
            float p = fmaf(v.x, v.x, fmaf(v.y, v.y, fmaf(v.z, v.z, v.w * v.w)));
#pragma unroll
            for (int o = 8; o; o >>= 1) p += __shfl_down_sync(0xFFFFFFFFu, p, o, 16);
            if ((t & 15) == 0) W2[col] = p;
        }
    }
    __syncthreads();

    // ---- phase 2: GEMM — warp owns rows 4*wid..4*wid+3; lane owns cols lane+32j ----
    float acc4[4][4] = {};
#pragma unroll
    for (int c = 0; c < 16; c++) {
        float4 xr[4], wv[4];
#pragma unroll
        for (int i = 0; i < 4; i++) xr[i] = X4[(4 * wid + i) * 16 + c];   // broadcast
#pragma unroll
        for (int j = 0; j < 4; j++) wv[j] = W4[c * 132 + lane + 32 * j];  // conflict-free
#pragma unroll
        for (int i = 0; i < 4; i++)
#pragma unroll
            for (int j = 0; j < 4; j++) {
                acc4[i][j] = fmaf(xr[i].x, wv[j].x, acc4[i][j]);
                acc4[i][j] = fmaf(xr[i].y, wv[j].y, acc4[i][j]);
                acc4[i][j] = fmaf(xr[i].z, wv[j].z, acc4[i][j]);
                acc4[i][j] = fmaf(xr[i].w, wv[j].w, acc4[i][j]);
            }
    }
    __syncthreads();   // all GEMM reads done before DIST/E alias writes (any warp)

    // ---- phase 3 (warp-local): epilogue — distances into smem DIST ----
#pragma unroll
    for (int i = 0; i < 4; i++) {
        int rl = 4 * wid + i;
        float x2v = X2[rl];
#pragma unroll
        for (int j = 0; j < 4; j++) {
            int col = lane + 32 * j;
            float d2 = fmaf(-2.0f, acc4[i][j], x2v + W2[col]);
            DIST[rl * K + col] = fsqrt_(fmaxf(d2, 0.0f));
        }
    }
    __syncwarp();

    // ---- phase 4 (warp-local): symmetric polys for this warp's 4 rows ----
    // lane handles row 4wid+(lane>>3), groups (lane&7)+8q
    {
        const int rl = 4 * wid + (lane >> 3);
        const int g0 = lane & 7;
#pragma unroll
        for (int qq = 0; qq < 4; qq++) {
            int g = g0 + 8 * qq;
            float4 dv = DIST4[rl * 32 + g];
            float b1 = fex2(fmaf(dv.x, 5.0f * LOG2E, -20.0f * LOG2E));
            float b2 = fex2(fmaf(dv.y, 5.0f * LOG2E, -20.0f * LOG2E));
            float b3 = fex2(fmaf(dv.z, 5.0f * LOG2E, -20.0f * LOG2E));
            float b4 = fex2(fmaf(dv.w, 5.0f * LOG2E, -20.0f * LOG2E));
            float s12 = b1 + b2, p12 = b1 * b2;
            float s34 = b3 + b4, p34 = b3 * b4;
            float4 e;
            e.x = s12 + s34;
            e.y = fmaf(s12, s34, p12 + p34);
            e.z = fmaf(p12, s34, p34 * s12);
            e.w = p12 * p34;
            E4[rl * 32 + g] = e;
        }
    }
    __syncwarp();

    // ---- phase 5 (warp-local): rank via Chebyshev fit, 4 rows ----
    const int node = lane & 15;
    const int half = lane >> 4;
    float acc = 0.0f;
#pragma unroll
    for (int rr = 0; rr < 4; rr++) {
        const int r = 4 * wid + rr;
        float d[4];
#pragma unroll
        for (int m = 0; m < 4; m++) d[m] = DIST[r * K + lane + 32 * m];

        float lmin = fminf(fminf(d[0], d[1]), fminf(d[2], d[3]));
        float lmax = fmaxf(fmaxf(d[0], d[1]), fmaxf(d[2], d[3]));
#pragma unroll
        for (int o = 16; o; o >>= 1) {
            lmin = fminf(lmin, __shfl_xor_sync(0xFFFFFFFFu, lmin, o));
            lmax = fmaxf(lmax, __shfl_xor_sync(0xFFFFFFFFu, lmax, o));
        }
        const float mid = 0.5f * (lmin + lmax);
        const float rad = fmaxf(0.5f * (lmax - lmin), 1e-5f);
        const float irad = frcp(rad);

        // exact f at node (lane&15); lane pair (l, l+16) splits the 32 groups
        const float tn = fmaf(rad, cosT[17 + node], mid);
        const float Av = fex2(fmaf(tn, 5.0f * LOG2E, -20.0f * LOG2E));
        float q = 0.0f;
#pragma unroll
        for (int g = 0; g < 16; g++) {
            float4 E = E4[r * 32 + half * 16 + g];
            float h1 = Av + E.x;
            float h2 = fmaf(h1, Av, E.y);
            float h3 = fmaf(h2, Av, E.z);
            float P  = fmaf(h3, Av, E.w);
            float g2 = h1 + Av;
            float g3 = fmaf(g2, Av, h2);
            float N  = fmaf(g3, Av, h3);
            q = fmaf(N, frcp(P), q);
        }
        q += __shfl_xor_sync(0xFFFFFFFFu, q, 16);
        const float fn = fmaf(Av, q, -64.0f);       // centered f(t_node)

        // 16-pt DCT: lane computes c_{lane&15}
        float c = 0.0f;
#pragma unroll
        for (int i = 0; i < NNODE; i++) {
            float fv = __shfl_sync(0xFFFFFFFFu, fn, i);
            c = fmaf(fv, cosT[node * 17 + i], c);
        }
        c *= (2.0f / NNODE);

        // Clenshaw, CHEB_M terms, 4 query points per lane
        const float c0h = 0.5f * __shfl_sync(0xFFFFFFFFu, c, 0);
        float y[4], y2[4], b1[4] = {}, b2[4] = {};
#pragma unroll
        for (int m = 0; m < 4; m++) {
            y[m] = (d[m] - mid) * irad;
            y2[m] = 2.0f * y[m];
        }
#pragma unroll
        for (int mm = CHEB_M - 1; mm >= 1; mm--) {
            float cm = __shfl_sync(0xFFFFFFFFu, c, mm);
#pragma unroll
            for (int m = 0; m < 4; m++) {
                float bn = fmaf(y2[m], b1[m], cm - b2[m]);
                b2[m] = b1[m]; b1[m] = bn;
            }
        }
#pragma unroll
        for (int m = 0; m < 4; m++) {
            float p = fmaf(y[m], b1[m], c0h - b2[m]);
            float rk = p + 63.5f;                   // +64 recenter, -0.5 diagonal
            acc = fmaf(fex2(-rk * (0.125f * LOG2E)), d[m], acc);
        }
    }

    // ---- block reduction -> global atomic ----
#pragma unroll
    for (int o = 16; o; o >>= 1) acc += __shfl_down_sync(0xFFFFFFFFu, acc, o);
    if (lane == 0) warp_sums[wid] = acc;
    __syncthreads();
    if (t == 0) {
        float s = 0.0f;
#pragma unroll
        for (int i = 0; i < 8; i++) s += warp_sums[i];
        atomicAdd(out, s * (1.0f / ((float)NROWS * (float)K)));
    }
}

extern "C" void kernel_launch(void* const* d_in, const int* in_sizes, int n_in,
                              void* d_out, int out_size)
{
    const float* data    = (const float*)d_in[0];
    const float* weights = (const float*)d_in[1];
    float* out = (float*)d_out;

    cudaMemsetAsync(out, 0, sizeof(float));
    dng_fused<<<NBLOCKS, 256>>>(data, weights, out);
}